// round 1
// baseline (speedup 1.0000x reference)
#include <cuda_runtime.h>
#include <math.h>

#define B_  2
#define S_  2048
#define D_  1024
#define H_  16
#define DK_ 64
#define NEGV  -1000000000.0f
#define SCALE 0.125f   // 1/sqrt(64)

// ---------------- scratch (no allocations allowed) ----------------
__device__ float g_Q[B_*H_*S_*DK_];   // [b,h,s,d]
__device__ float g_K[B_*H_*S_*DK_];
__device__ float g_V[B_*H_*S_*DK_];
__device__ float g_ctx[B_*S_*D_];     // [b,s,h*d]

// ---------------- GEMM: Y[m,n] = sum_k X[m,k]*W[n,k] + bias[n] ----------------
// M=4096, N=1024, K=1024 fixed. 128x128x16 tile, 256 threads, 8x8 per thread.
#define GM 4096
#define GN 1024
#define GK 1024
#define BM 128
#define BN 128
#define BKK 16

__global__ __launch_bounds__(256)
void gemm_nt(const float* __restrict__ X, const float* __restrict__ W,
             const float* __restrict__ bias,
             float* __restrict__ Yplain,   // [M,N] row-major (or null)
             float* __restrict__ Ybhsd)    // [b,h,s,d] layout (or null)
{
    __shared__ float As[BKK][BM + 4];
    __shared__ float Bs[BKK][BN + 4];

    const int tid = threadIdx.x;
    const int tx = tid & 15;        // 0..15 -> n
    const int ty = tid >> 4;        // 0..15 -> m
    const int m0 = blockIdx.y * BM;
    const int n0 = blockIdx.x * BN;

    float acc[8][8];
#pragma unroll
    for (int i = 0; i < 8; i++)
#pragma unroll
        for (int j = 0; j < 8; j++) acc[i][j] = 0.0f;

    for (int k0 = 0; k0 < GK; k0 += BKK) {
        // load A,B tiles (transposed into smem). 512 float4 each, 2 per thread.
#pragma unroll
        for (int it = 0; it < 2; it++) {
            int idx = tid + it * 256;          // 0..511
            int row = idx >> 2;                // 0..127
            int kq  = (idx & 3) * 4;           // 0,4,8,12
            float4 a = *(const float4*)(X + (m0 + row) * GK + k0 + kq);
            As[kq+0][row] = a.x; As[kq+1][row] = a.y;
            As[kq+2][row] = a.z; As[kq+3][row] = a.w;
            float4 b = *(const float4*)(W + (n0 + row) * GK + k0 + kq);
            Bs[kq+0][row] = b.x; Bs[kq+1][row] = b.y;
            Bs[kq+2][row] = b.z; Bs[kq+3][row] = b.w;
        }
        __syncthreads();

#pragma unroll
        for (int kk = 0; kk < BKK; kk++) {
            float af[8], bf[8];
            const float4* ap = (const float4*)&As[kk][ty * 8];
            const float4* bp = (const float4*)&Bs[kk][tx * 8];
            float4 a0 = ap[0], a1 = ap[1];
            float4 b0 = bp[0], b1 = bp[1];
            af[0]=a0.x; af[1]=a0.y; af[2]=a0.z; af[3]=a0.w;
            af[4]=a1.x; af[5]=a1.y; af[6]=a1.z; af[7]=a1.w;
            bf[0]=b0.x; bf[1]=b0.y; bf[2]=b0.z; bf[3]=b0.w;
            bf[4]=b1.x; bf[5]=b1.y; bf[6]=b1.z; bf[7]=b1.w;
#pragma unroll
            for (int i = 0; i < 8; i++)
#pragma unroll
                for (int j = 0; j < 8; j++)
                    acc[i][j] += af[i] * bf[j];
        }
        __syncthreads();
    }

    // epilogue
#pragma unroll
    for (int i = 0; i < 8; i++) {
        int m = m0 + ty * 8 + i;
#pragma unroll
        for (int j = 0; j < 8; j++) {
            int n = n0 + tx * 8 + j;
            float v = acc[i][j] + bias[n];
            if (Yplain) {
                Yplain[m * GN + n] = v;
            } else {
                int b = m >> 11;          // /S_
                int s = m & (S_ - 1);
                int h = n >> 6;           // /DK_
                int d = n & (DK_ - 1);
                Ybhsd[(((b * H_ + h) * S_) + s) * DK_ + d] = v;
            }
        }
    }
}

// ---------------- flash attention ----------------
// grid: (S/64, H, B); block 256 threads (16x16), 64 q-rows x 64 kv per tile.
// thread (ty,tx): score/out tile rows ty*4+i, cols tx*4+j.
__global__ __launch_bounds__(256)
void attn_kernel(const int* __restrict__ mask)
{
    extern __shared__ float sm[];
    float* Qs = sm;                 // [64][64]  stride 64
    float* Ks = Qs + 64 * 64;       // [64][65]  stride 65 (reused as Ps)
    float* Vs = Ks + 64 * 65;       // [64][65]
    int*   mks = (int*)(Vs + 64 * 65); // [64]

    const int tid = threadIdx.x;
    const int tx = tid & 15;
    const int ty = tid >> 4;
    const int q0 = blockIdx.x * 64;
    const int h  = blockIdx.y;
    const int b  = blockIdx.z;

    const float* Qg = g_Q + ((b * H_ + h) * S_ + q0) * DK_;
    const float* Kbase = g_K + (b * H_ + h) * S_ * DK_;
    const float* Vbase = g_V + (b * H_ + h) * S_ * DK_;

    // load Q tile
    for (int t = tid; t < 64 * 64; t += 256) Qs[t] = Qg[t];

    int mq[4];
#pragma unroll
    for (int i = 0; i < 4; i++)
        mq[i] = mask[b * S_ + q0 + ty * 4 + i];

    float m_run[4], l_run[4], acc[4][4];
#pragma unroll
    for (int i = 0; i < 4; i++) {
        m_run[i] = -INFINITY;
        l_run[i] = 0.0f;
#pragma unroll
        for (int j = 0; j < 4; j++) acc[i][j] = 0.0f;
    }
    __syncthreads();

    for (int kt = 0; kt < S_ / 64; kt++) {
        const float* Kg = Kbase + kt * 64 * DK_;
        const float* Vg = Vbase + kt * 64 * DK_;
        for (int t = tid; t < 64 * 64; t += 256) {
            int row = t >> 6, col = t & 63;
            Ks[row * 65 + col] = Kg[t];
            Vs[row * 65 + col] = Vg[t];
        }
        if (tid < 64) mks[tid] = mask[b * S_ + kt * 64 + tid];
        __syncthreads();

        // scores: s[i][j] = Q[row_i] . K[col_j]
        float sr[4][4];
#pragma unroll
        for (int i = 0; i < 4; i++)
#pragma unroll
            for (int j = 0; j < 4; j++) sr[i][j] = 0.0f;

#pragma unroll 8
        for (int kk = 0; kk < 64; kk++) {
            float af[4], bf[4];
#pragma unroll
            for (int i = 0; i < 4; i++) af[i] = Qs[(ty * 4 + i) * 64 + kk];
#pragma unroll
            for (int j = 0; j < 4; j++) bf[j] = Ks[(tx * 4 + j) * 65 + kk];
#pragma unroll
            for (int i = 0; i < 4; i++)
#pragma unroll
                for (int j = 0; j < 4; j++)
                    sr[i][j] += af[i] * bf[j];
        }

        int mk[4];
#pragma unroll
        for (int j = 0; j < 4; j++) mk[j] = mks[tx * 4 + j];

#pragma unroll
        for (int i = 0; i < 4; i++)
#pragma unroll
            for (int j = 0; j < 4; j++)
                sr[i][j] = (mq[i] != 0 && mk[j] != 0) ? sr[i][j] * SCALE : NEGV;

        // row max across the 16 tx-threads (lanes differ only in low 4 bits)
        float mt[4];
#pragma unroll
        for (int i = 0; i < 4; i++) {
            float v = fmaxf(fmaxf(sr[i][0], sr[i][1]), fmaxf(sr[i][2], sr[i][3]));
#pragma unroll
            for (int off = 1; off < 16; off <<= 1)
                v = fmaxf(v, __shfl_xor_sync(0xffffffffu, v, off));
            mt[i] = v;
        }

        float alpha[4], m_new[4], rs[4];
#pragma unroll
        for (int i = 0; i < 4; i++) {
            m_new[i] = fmaxf(m_run[i], mt[i]);
            alpha[i] = __expf(m_run[i] - m_new[i]);   // exp(-inf)=0 on first tile
            m_run[i] = m_new[i];
        }

        float p[4][4];
#pragma unroll
        for (int i = 0; i < 4; i++) {
            float s = 0.0f;
#pragma unroll
            for (int j = 0; j < 4; j++) {
                p[i][j] = __expf(sr[i][j] - m_new[i]);
                s += p[i][j];
            }
#pragma unroll
            for (int off = 1; off < 16; off <<= 1)
                s += __shfl_xor_sync(0xffffffffu, s, off);
            rs[i] = s;
        }

#pragma unroll
        for (int i = 0; i < 4; i++) {
            l_run[i] = l_run[i] * alpha[i] + rs[i];
#pragma unroll
            for (int j = 0; j < 4; j++) acc[i][j] *= alpha[i];
        }

        // store P into Ks region (Ks no longer needed this tile)
        __syncthreads();
#pragma unroll
        for (int i = 0; i < 4; i++)
#pragma unroll
            for (int j = 0; j < 4; j++)
                Ks[(ty * 4 + i) * 65 + tx * 4 + j] = p[i][j];
        __syncthreads();

        // O += P @ V
#pragma unroll 8
        for (int jj = 0; jj < 64; jj++) {
            float pf[4], vf[4];
#pragma unroll
            for (int i = 0; i < 4; i++) pf[i] = Ks[(ty * 4 + i) * 65 + jj];
#pragma unroll
            for (int j = 0; j < 4; j++) vf[j] = Vs[jj * 65 + tx * 4 + j];
#pragma unroll
            for (int i = 0; i < 4; i++)
#pragma unroll
                for (int j = 0; j < 4; j++)
                    acc[i][j] += pf[i] * vf[j];
        }
        __syncthreads();   // before next tile overwrites Ks/Vs
    }

    // epilogue: ctx[b, s, h*64+d] = acc / l
#pragma unroll
    for (int i = 0; i < 4; i++) {
        int srow = q0 + ty * 4 + i;
        float inv = 1.0f / l_run[i];
#pragma unroll
        for (int j = 0; j < 4; j++) {
            int d = tx * 4 + j;
            g_ctx[(b * S_ + srow) * D_ + h * DK_ + d] = acc[i][j] * inv;
        }
    }
}

// ---------------- host ----------------
extern "C" void kernel_launch(void* const* d_in, const int* in_sizes, int n_in,
                              void* d_out, int out_size)
{
    const float* query = (const float*)d_in[0];
    const float* key   = (const float*)d_in[1];
    const float* value = (const float*)d_in[2];
    const int*   mask  = (const int*)  d_in[3];
    const float* wq = (const float*)d_in[4];
    const float* bq = (const float*)d_in[5];
    const float* wk = (const float*)d_in[6];
    const float* bk = (const float*)d_in[7];
    const float* wv = (const float*)d_in[8];
    const float* bv = (const float*)d_in[9];
    const float* wo = (const float*)d_in[10];
    const float* bo = (const float*)d_in[11];

    float *gQ, *gK, *gV, *gctx;
    cudaGetSymbolAddress((void**)&gQ,   g_Q);
    cudaGetSymbolAddress((void**)&gK,   g_K);
    cudaGetSymbolAddress((void**)&gV,   g_V);
    cudaGetSymbolAddress((void**)&gctx, g_ctx);

    dim3 gg(GN / BN, GM / BM);   // (8, 32)

    gemm_nt<<<gg, 256>>>(query, wq, bq, nullptr, gQ);
    gemm_nt<<<gg, 256>>>(key,   wk, bk, nullptr, gK);
    gemm_nt<<<gg, 256>>>(value, wv, bv, nullptr, gV);

    const int smem = (64*64 + 64*65 + 64*65) * 4 + 64 * 4;  // 49920 B
    cudaFuncSetAttribute(attn_kernel,
                         cudaFuncAttributeMaxDynamicSharedMemorySize, smem);
    attn_kernel<<<dim3(S_ / 64, H_, B_), 256, smem>>>(mask);

    gemm_nt<<<gg, 256>>>(gctx, wo, bo, (float*)d_out, nullptr);
}

// round 3
// speedup vs baseline: 2.7780x; 2.7780x over previous
#include <cuda_runtime.h>
#include <math.h>

#define B_  2
#define S_  2048
#define D_  1024
#define H_  16
#define DK_ 64
#define NEGV  -1000000000.0f

// ---------------- scratch (no allocations allowed) ----------------
__device__ float g_Q[B_*H_*S_*DK_];   // [b,h,s,d]  (pre-scaled by 1/8)
__device__ float g_K[B_*H_*S_*DK_];
__device__ float g_V[B_*H_*S_*DK_];
__device__ float g_ctx[B_*S_*D_];     // [b,s,h*d]

// ---------------- tf32 helpers ----------------
__device__ __forceinline__ unsigned f2tf(float x) {
    unsigned r; asm("cvt.rna.tf32.f32 %0, %1;" : "=r"(r) : "f"(x)); return r;
}
__device__ __forceinline__ float f2tff(float x) { return __uint_as_float(f2tf(x)); }

__device__ __forceinline__ void mma8(float* c, const unsigned* a, unsigned b0, unsigned b1) {
    asm volatile(
        "mma.sync.aligned.m16n8k8.row.col.f32.tf32.tf32.f32 "
        "{%0,%1,%2,%3}, {%4,%5,%6,%7}, {%8,%9}, {%0,%1,%2,%3};"
        : "+f"(c[0]), "+f"(c[1]), "+f"(c[2]), "+f"(c[3])
        : "r"(a[0]), "r"(a[1]), "r"(a[2]), "r"(a[3]), "r"(b0), "r"(b1));
}

// ---------------- GEMM: Y[m,n] = (sum_k X[m,k]*W[n,k] + bias[n]) * scale ----
// M=4096, N=1024, K=1024. CTA tile 128x128x32, 8 warps (2x4), warp tile 64x32.
#define GK 1024
#define GN 1024

__global__ __launch_bounds__(256)
void gemm_tf32(const float* __restrict__ X, const float* __restrict__ W,
               const float* __restrict__ bias, float scale,
               float* __restrict__ Yplain,   // [M,N] row-major (or null)
               float* __restrict__ Ybhsd)    // [b,h,s,d] layout (or null)
{
    __shared__ float Xs[128][36];
    __shared__ float Ws[128][36];

    const int tid  = threadIdx.x;
    const int lane = tid & 31;
    const int wid  = tid >> 5;
    const int g = lane >> 2, q = lane & 3;
    const int wm = wid >> 2, wn = wid & 3;          // 2 x 4 warp grid
    const int m0 = blockIdx.y * 128, n0 = blockIdx.x * 128;

    float c[4][4][4];
#pragma unroll
    for (int i = 0; i < 4; i++)
#pragma unroll
        for (int j = 0; j < 4; j++)
#pragma unroll
            for (int k = 0; k < 4; k++) c[i][j][k] = 0.0f;

    for (int k0 = 0; k0 < GK; k0 += 32) {
#pragma unroll
        for (int i = 0; i < 4; i++) {
            int idx = tid + i * 256;                // 0..1023
            int row = idx >> 3;                     // 0..127
            int cc  = (idx & 7) * 4;                // 0..28
            float4 xv = *(const float4*)(X + (size_t)(m0 + row) * GK + k0 + cc);
            Xs[row][cc+0] = f2tff(xv.x); Xs[row][cc+1] = f2tff(xv.y);
            Xs[row][cc+2] = f2tff(xv.z); Xs[row][cc+3] = f2tff(xv.w);
            float4 wv = *(const float4*)(W + (size_t)(n0 + row) * GK + k0 + cc);
            Ws[row][cc+0] = f2tff(wv.x); Ws[row][cc+1] = f2tff(wv.y);
            Ws[row][cc+2] = f2tff(wv.z); Ws[row][cc+3] = f2tff(wv.w);
        }
        __syncthreads();

#pragma unroll
        for (int ks = 0; ks < 4; ks++) {
            const int k8 = ks * 8;
            unsigned a[4][4], bb[4][2];
#pragma unroll
            for (int im = 0; im < 4; im++) {
                int rb = wm * 64 + im * 16;
                a[im][0] = __float_as_uint(Xs[rb + g    ][k8 + q    ]);
                a[im][1] = __float_as_uint(Xs[rb + g + 8][k8 + q    ]);
                a[im][2] = __float_as_uint(Xs[rb + g    ][k8 + q + 4]);
                a[im][3] = __float_as_uint(Xs[rb + g + 8][k8 + q + 4]);
            }
#pragma unroll
            for (int jn = 0; jn < 4; jn++) {
                int nb = wn * 32 + jn * 8 + g;
                bb[jn][0] = __float_as_uint(Ws[nb][k8 + q    ]);
                bb[jn][1] = __float_as_uint(Ws[nb][k8 + q + 4]);
            }
#pragma unroll
            for (int im = 0; im < 4; im++)
#pragma unroll
                for (int jn = 0; jn < 4; jn++)
                    mma8(c[im][jn], a[im], bb[jn][0], bb[jn][1]);
        }
        __syncthreads();
    }

    // epilogue
#pragma unroll
    for (int im = 0; im < 4; im++) {
#pragma unroll
        for (int jn = 0; jn < 4; jn++) {
            int n = n0 + wn * 32 + jn * 8 + 2 * q;
            float b0v = bias[n], b1v = bias[n + 1];
            int mA = m0 + wm * 64 + im * 16 + g;
            int mB = mA + 8;
            float v0 = (c[im][jn][0] + b0v) * scale;
            float v1 = (c[im][jn][1] + b1v) * scale;
            float v2 = (c[im][jn][2] + b0v) * scale;
            float v3 = (c[im][jn][3] + b1v) * scale;
            if (Yplain) {
                *(float2*)(Yplain + (size_t)mA * GN + n) = make_float2(v0, v1);
                *(float2*)(Yplain + (size_t)mB * GN + n) = make_float2(v2, v3);
            } else {
                int h = n >> 6, d = n & 63;
                {
                    int b = mA >> 11, s = mA & (S_ - 1);
                    *(float2*)(Ybhsd + (size_t)(((b*H_ + h)*S_) + s)*DK_ + d) = make_float2(v0, v1);
                }
                {
                    int b = mB >> 11, s = mB & (S_ - 1);
                    *(float2*)(Ybhsd + (size_t)(((b*H_ + h)*S_) + s)*DK_ + d) = make_float2(v2, v3);
                }
            }
        }
    }
}

// ---------------- flash attention (tf32 tensor core) ----------------
// grid: (S/128, H, B); block 256 = 8 warps; each warp owns 16 q-rows.
__global__ __launch_bounds__(256)
void attn_tf32(const int* __restrict__ mask)
{
    extern __shared__ float sm[];
    float* Qs = sm;                       // [128][68], later reused as P
    float* Ks = Qs + 128 * 68;            // [64][68]
    float* Vs = Ks + 64 * 68;             // [64][68]
    int*   mks = (int*)(Vs + 64 * 68);    // [64]

    const int tid  = threadIdx.x;
    const int lane = tid & 31;
    const int wid  = tid >> 5;
    const int g = lane >> 2, q = lane & 3;
    const int q0 = blockIdx.x * 128;
    const int h  = blockIdx.y;
    const int b  = blockIdx.z;
    const int wb = wid * 16;

    const float* Qg = g_Q + (size_t)((b*H_ + h)*S_ + q0) * DK_;
    const float* Kb = g_K + (size_t)(b*H_ + h) * S_ * DK_;
    const float* Vb = g_V + (size_t)(b*H_ + h) * S_ * DK_;

    // load Q tile (tf32-rounded): 128x64 = 2048 float4, 8 per thread
#pragma unroll
    for (int i = 0; i < 8; i++) {
        int idx = tid + i * 256;
        int row = idx >> 4, c4 = (idx & 15) * 4;
        float4 v = *(const float4*)(Qg + row * 64 + c4);
        float* d = Qs + row * 68 + c4;
        d[0] = f2tff(v.x); d[1] = f2tff(v.y); d[2] = f2tff(v.z); d[3] = f2tff(v.w);
    }
    __syncthreads();

    // Q fragments (register-resident for whole kernel)
    unsigned qa[8][4];
#pragma unroll
    for (int kk = 0; kk < 8; kk++) {
        int k8 = kk * 8;
        qa[kk][0] = __float_as_uint(Qs[(wb + g    ) * 68 + k8 + q    ]);
        qa[kk][1] = __float_as_uint(Qs[(wb + g + 8) * 68 + k8 + q    ]);
        qa[kk][2] = __float_as_uint(Qs[(wb + g    ) * 68 + k8 + q + 4]);
        qa[kk][3] = __float_as_uint(Qs[(wb + g + 8) * 68 + k8 + q + 4]);
    }
    const bool mr1 = mask[b*S_ + q0 + wb + g    ] != 0;
    const bool mr2 = mask[b*S_ + q0 + wb + g + 8] != 0;

    float m1 = -INFINITY, m2 = -INFINITY, l1 = 0.0f, l2 = 0.0f;
    float o[8][4];
#pragma unroll
    for (int j = 0; j < 8; j++)
#pragma unroll
        for (int k = 0; k < 4; k++) o[j][k] = 0.0f;

    float* Pw = Qs + wb * 68;    // warp-private 16x68 region (old Q rows)

    for (int kt = 0; kt < S_ / 64; kt++) {
        __syncthreads();   // prev iter's PV reads of Vs done
#pragma unroll
        for (int i = 0; i < 4; i++) {
            int idx = tid + i * 256;
            int row = idx >> 4, c4 = (idx & 15) * 4;
            float4 kv = *(const float4*)(Kb + (size_t)(kt*64 + row) * 64 + c4);
            float* dk_ = Ks + row * 68 + c4;
            dk_[0] = f2tff(kv.x); dk_[1] = f2tff(kv.y); dk_[2] = f2tff(kv.z); dk_[3] = f2tff(kv.w);
            float4 vv = *(const float4*)(Vb + (size_t)(kt*64 + row) * 64 + c4);
            float* dv = Vs + row * 68 + c4;
            dv[0] = f2tff(vv.x); dv[1] = f2tff(vv.y); dv[2] = f2tff(vv.z); dv[3] = f2tff(vv.w);
        }
        if (tid < 64) mks[tid] = mask[b*S_ + kt*64 + tid];
        __syncthreads();

        // S = Q @ K^T
        float s[8][4];
#pragma unroll
        for (int j = 0; j < 8; j++) {
            s[j][0] = s[j][1] = s[j][2] = s[j][3] = 0.0f;
#pragma unroll
            for (int kk = 0; kk < 8; kk++) {
                unsigned b0 = __float_as_uint(Ks[(j*8 + g) * 68 + kk*8 + q    ]);
                unsigned b1 = __float_as_uint(Ks[(j*8 + g) * 68 + kk*8 + q + 4]);
                mma8(s[j], qa[kk], b0, b1);
            }
        }

        // mask (scale already folded into Q)
#pragma unroll
        for (int j = 0; j < 8; j++) {
            int c0 = j*8 + 2*q;
            bool k0m = mks[c0] != 0, k1m = mks[c0 + 1] != 0;
            s[j][0] = (mr1 && k0m) ? s[j][0] : NEGV;
            s[j][1] = (mr1 && k1m) ? s[j][1] : NEGV;
            s[j][2] = (mr2 && k0m) ? s[j][2] : NEGV;
            s[j][3] = (mr2 && k1m) ? s[j][3] : NEGV;
        }

        // online softmax
        float t1 = -INFINITY, t2 = -INFINITY;
#pragma unroll
        for (int j = 0; j < 8; j++) {
            t1 = fmaxf(t1, fmaxf(s[j][0], s[j][1]));
            t2 = fmaxf(t2, fmaxf(s[j][2], s[j][3]));
        }
        t1 = fmaxf(t1, __shfl_xor_sync(0xffffffffu, t1, 1));
        t1 = fmaxf(t1, __shfl_xor_sync(0xffffffffu, t1, 2));
        t2 = fmaxf(t2, __shfl_xor_sync(0xffffffffu, t2, 1));
        t2 = fmaxf(t2, __shfl_xor_sync(0xffffffffu, t2, 2));

        float n1 = fmaxf(m1, t1), n2 = fmaxf(m2, t2);
        float a1 = __expf(m1 - n1), a2 = __expf(m2 - n2);
        m1 = n1; m2 = n2;

        float r1 = 0.0f, r2 = 0.0f;
#pragma unroll
        for (int j = 0; j < 8; j++) {
            s[j][0] = __expf(s[j][0] - n1); s[j][1] = __expf(s[j][1] - n1);
            s[j][2] = __expf(s[j][2] - n2); s[j][3] = __expf(s[j][3] - n2);
            r1 += s[j][0] + s[j][1];
            r2 += s[j][2] + s[j][3];
        }
        r1 += __shfl_xor_sync(0xffffffffu, r1, 1);
        r1 += __shfl_xor_sync(0xffffffffu, r1, 2);
        r2 += __shfl_xor_sync(0xffffffffu, r2, 1);
        r2 += __shfl_xor_sync(0xffffffffu, r2, 2);
        l1 = l1 * a1 + r1;
        l2 = l2 * a2 + r2;
#pragma unroll
        for (int j = 0; j < 8; j++) {
            o[j][0] *= a1; o[j][1] *= a1; o[j][2] *= a2; o[j][3] *= a2;
        }

        // store P (warp-private region), then O += P @ V
#pragma unroll
        for (int j = 0; j < 8; j++) {
            int c0 = j*8 + 2*q;
            *(float2*)(Pw + (g    ) * 68 + c0) = make_float2(f2tff(s[j][0]), f2tff(s[j][1]));
            *(float2*)(Pw + (g + 8) * 68 + c0) = make_float2(f2tff(s[j][2]), f2tff(s[j][3]));
        }
        __syncwarp();

#pragma unroll
        for (int kk = 0; kk < 8; kk++) {
            unsigned pa[4];
            pa[0] = __float_as_uint(Pw[(g    ) * 68 + kk*8 + q    ]);
            pa[1] = __float_as_uint(Pw[(g + 8) * 68 + kk*8 + q    ]);
            pa[2] = __float_as_uint(Pw[(g    ) * 68 + kk*8 + q + 4]);
            pa[3] = __float_as_uint(Pw[(g + 8) * 68 + kk*8 + q + 4]);
#pragma unroll
            for (int j = 0; j < 8; j++) {
                unsigned b0 = __float_as_uint(Vs[(kk*8 + q    ) * 68 + j*8 + g]);
                unsigned b1 = __float_as_uint(Vs[(kk*8 + q + 4) * 68 + j*8 + g]);
                mma8(o[j], pa, b0, b1);
            }
        }
        __syncwarp();
    }

    // epilogue: ctx[b, s, h*64+d] = o / l
    float i1 = 1.0f / l1, i2 = 1.0f / l2;
    int r1g = q0 + wb + g, r2g = r1g + 8;
#pragma unroll
    for (int j = 0; j < 8; j++) {
        int col = h * 64 + j*8 + 2*q;
        *(float2*)(g_ctx + (size_t)(b*S_ + r1g) * D_ + col) = make_float2(o[j][0]*i1, o[j][1]*i1);
        *(float2*)(g_ctx + (size_t)(b*S_ + r2g) * D_ + col) = make_float2(o[j][2]*i2, o[j][3]*i2);
    }
}

// ---------------- host ----------------
extern "C" void kernel_launch(void* const* d_in, const int* in_sizes, int n_in,
                              void* d_out, int out_size)
{
    const float* query = (const float*)d_in[0];
    const float* key   = (const float*)d_in[1];
    const float* value = (const float*)d_in[2];
    const int*   mask  = (const int*)  d_in[3];
    const float* wq = (const float*)d_in[4];
    const float* bq = (const float*)d_in[5];
    const float* wk = (const float*)d_in[6];
    const float* bk = (const float*)d_in[7];
    const float* wv = (const float*)d_in[8];
    const float* bv = (const float*)d_in[9];
    const float* wo = (const float*)d_in[10];
    const float* bo = (const float*)d_in[11];

    float *gQ, *gK, *gV, *gctx;
    cudaGetSymbolAddress((void**)&gQ,   g_Q);
    cudaGetSymbolAddress((void**)&gK,   g_K);
    cudaGetSymbolAddress((void**)&gV,   g_V);
    cudaGetSymbolAddress((void**)&gctx, g_ctx);

    dim3 gg(GN / 128, 4096 / 128);   // (8, 32)

    gemm_tf32<<<gg, 256>>>(query, wq, bq, 0.125f, nullptr, gQ);  // fold 1/sqrt(dk)
    gemm_tf32<<<gg, 256>>>(key,   wk, bk, 1.0f,   nullptr, gK);
    gemm_tf32<<<gg, 256>>>(value, wv, bv, 1.0f,   nullptr, gV);

    const int smem = (128*68 + 64*68 + 64*68) * 4 + 64 * 4;  // 69888 B
    cudaFuncSetAttribute(attn_tf32,
                         cudaFuncAttributeMaxDynamicSharedMemorySize, smem);
    attn_tf32<<<dim3(S_/128, H_, B_), 256, smem>>>(mask);

    gemm_tf32<<<gg, 256>>>(gctx, wo, bo, 1.0f, (float*)d_out, nullptr);
}

// round 4
// speedup vs baseline: 2.8644x; 1.0311x over previous
#include <cuda_runtime.h>
#include <math.h>

#define B_  2
#define S_  2048
#define D_  1024
#define H_  16
#define DK_ 64
#define NEGV  -1000000000.0f

// ---------------- scratch ----------------
// g_Q, g_K: packed per-row layout  [b,h,s, perm8(d)]  perm8(d) = (d&3)*16 + (d>>2)
// g_V: transposed packed           [b,h,d, 64*tile + perm8(s&63)]
__device__ float g_Q[B_*H_*S_*DK_];
__device__ float g_K[B_*H_*S_*DK_];
__device__ float g_V[B_*H_*S_*DK_];
__device__ float g_ctx[B_*S_*D_];     // [b,s,h*d]

__device__ __forceinline__ unsigned f2tf(float x) {
    unsigned r; asm("cvt.rna.tf32.f32 %0, %1;" : "=r"(r) : "f"(x)); return r;
}
__device__ __forceinline__ float f2tff(float x) { return __uint_as_float(f2tf(x)); }
__device__ __forceinline__ unsigned uf(float x) { return __float_as_uint(x); }

__device__ __forceinline__ void mma8(float* c, const unsigned* a, unsigned b0, unsigned b1) {
    asm volatile(
        "mma.sync.aligned.m16n8k8.row.col.f32.tf32.tf32.f32 "
        "{%0,%1,%2,%3}, {%4,%5,%6,%7}, {%8,%9}, {%0,%1,%2,%3};"
        : "+f"(c[0]), "+f"(c[1]), "+f"(c[2]), "+f"(c[3])
        : "r"(a[0]), "r"(a[1]), "r"(a[2]), "r"(a[3]), "r"(b0), "r"(b1));
}

// ---------------- GEMM: Y[m,n] = (sum_k X[m,k]*W[n,k] + bias[n]) * scale ----
// M=4096, N=1024, K=1024. CTA 128x128x32, 8 warps (2x4), warp tile 64x32.
// smem layout: per row 32 k-values permuted: pos = (k&3)*8 + (k>>2), stride 36.
// modes: 0 = plain [M,N] fp32 out; 1 = packed bhsd (Q/K, tf32-rounded);
//        2 = transposed packed (V, tf32-rounded).
#define GK 1024
#define GN 1024

__global__ __launch_bounds__(256, 2)
void gemm_tf32(const float* __restrict__ X, const float* __restrict__ W,
               const float* __restrict__ bias, float scale,
               float* __restrict__ Y, int mode)
{
    __shared__ float Xs[128 * 36];
    __shared__ float Ws[128 * 36];

    const int tid  = threadIdx.x;
    const int lane = tid & 31;
    const int wid  = tid >> 5;
    const int g = lane >> 2, q = lane & 3;
    const int wm = wid >> 2, wn = wid & 3;
    const int m0 = blockIdx.y * 128, n0 = blockIdx.x * 128;

    float c[4][4][4];
#pragma unroll
    for (int i = 0; i < 4; i++)
#pragma unroll
        for (int j = 0; j < 4; j++)
#pragma unroll
            for (int k = 0; k < 4; k++) c[i][j][k] = 0.0f;

    for (int k0 = 0; k0 < GK; k0 += 32) {
#pragma unroll
        for (int i = 0; i < 4; i++) {
            int idx = tid + i * 256;            // 0..1023
            int row = idx >> 3;                 // 0..127
            int kq  = (idx & 7) * 4;            // 0..28
            int base = row * 36 + (kq >> 2);
            float4 xv = *(const float4*)(X + (size_t)(m0 + row) * GK + k0 + kq);
            Xs[base     ] = f2tff(xv.x);
            Xs[base +  8] = f2tff(xv.y);
            Xs[base + 16] = f2tff(xv.z);
            Xs[base + 24] = f2tff(xv.w);
            float4 wv = *(const float4*)(W + (size_t)(n0 + row) * GK + k0 + kq);
            Ws[base     ] = f2tff(wv.x);
            Ws[base +  8] = f2tff(wv.y);
            Ws[base + 16] = f2tff(wv.z);
            Ws[base + 24] = f2tff(wv.w);
        }
        __syncthreads();

#pragma unroll
        for (int p = 0; p < 2; p++) {
            const int cofs = q * 8 + 4 * p;
            unsigned bb[4][4];
#pragma unroll
            for (int jn = 0; jn < 4; jn++) {
                int nb = wn * 32 + jn * 8 + g;
                float4 wr = *(const float4*)(Ws + nb * 36 + cofs);
                bb[jn][0] = uf(wr.x); bb[jn][1] = uf(wr.y);
                bb[jn][2] = uf(wr.z); bb[jn][3] = uf(wr.w);
            }
#pragma unroll
            for (int im = 0; im < 4; im++) {
                int rb = wm * 64 + im * 16;
                float4 ar = *(const float4*)(Xs + (rb + g    ) * 36 + cofs);
                float4 br = *(const float4*)(Xs + (rb + g + 8) * 36 + cofs);
                unsigned aE[4] = { uf(ar.x), uf(br.x), uf(ar.y), uf(br.y) };
                unsigned aO[4] = { uf(ar.z), uf(br.z), uf(ar.w), uf(br.w) };
#pragma unroll
                for (int jn = 0; jn < 4; jn++) {
                    mma8(c[im][jn], aE, bb[jn][0], bb[jn][1]);
                    mma8(c[im][jn], aO, bb[jn][2], bb[jn][3]);
                }
            }
        }
        __syncthreads();
    }

    // epilogue
#pragma unroll
    for (int im = 0; im < 4; im++) {
#pragma unroll
        for (int jn = 0; jn < 4; jn++) {
            int n  = n0 + wn * 32 + jn * 8 + 2 * q;
            int mA = m0 + wm * 64 + im * 16 + g;
            int mB = mA + 8;
            float b0v = bias[n], b1v = bias[n + 1];
            float v0 = (c[im][jn][0] + b0v) * scale;
            float v1 = (c[im][jn][1] + b1v) * scale;
            float v2 = (c[im][jn][2] + b0v) * scale;
            float v3 = (c[im][jn][3] + b1v) * scale;
            if (mode == 0) {
                *(float2*)(Y + (size_t)mA * GN + n) = make_float2(v0, v1);
                *(float2*)(Y + (size_t)mB * GN + n) = make_float2(v2, v3);
            } else if (mode == 1) {
                // packed bhsd: ((b*H+h)*S + s)*64 + (d&3)*16 + (d>>2)
                int h = n >> 6, d0 = n & 63, d1 = d0 + 1;
                int p0 = (d0 & 3) * 16 + (d0 >> 2);
                int p1 = (d1 & 3) * 16 + (d1 >> 2);
                {
                    int b = mA >> 11, s = mA & (S_ - 1);
                    float* base = Y + (size_t)((b*H_ + h)*S_ + s) * 64;
                    base[p0] = f2tff(v0); base[p1] = f2tff(v1);
                }
                {
                    int b = mB >> 11, s = mB & (S_ - 1);
                    float* base = Y + (size_t)((b*H_ + h)*S_ + s) * 64;
                    base[p0] = f2tff(v2); base[p1] = f2tff(v3);
                }
            } else {
                // V transposed packed: ((b*H+h)*64 + d)*S + (s&~63) + (s&3)*16 + ((s&63)>>2)
                int h = n >> 6, d0 = n & 63, d1 = d0 + 1;
                {
                    int b = mA >> 11, s = mA & (S_ - 1);
                    int ps = (s & ~63) + (s & 3) * 16 + ((s & 63) >> 2);
                    Y[(size_t)((b*H_ + h)*64 + d0) * S_ + ps] = f2tff(v0);
                    Y[(size_t)((b*H_ + h)*64 + d1) * S_ + ps] = f2tff(v1);
                }
                {
                    int b = mB >> 11, s = mB & (S_ - 1);
                    int ps = (s & ~63) + (s & 3) * 16 + ((s & 63) >> 2);
                    Y[(size_t)((b*H_ + h)*64 + d0) * S_ + ps] = f2tff(v2);
                    Y[(size_t)((b*H_ + h)*64 + d1) * S_ + ps] = f2tff(v3);
                }
            }
        }
    }
}

// ---------------- flash attention (tf32, packed frags, shuffle-P) ----------
// grid: (S/64, H, B); block 128 = 4 warps; warp owns 16 q-rows.
// smem tiles [64 rows][64], 16B-chunk index XOR-swizzled by row parity.
__global__ __launch_bounds__(128, 3)
void attn_tf32(const int* __restrict__ mask)
{
    __shared__ float Ks[64 * 64];
    __shared__ float Vs[64 * 64];
    __shared__ int   mks[64];

    const int tid  = threadIdx.x;
    const int lane = tid & 31;
    const int wid  = tid >> 5;
    const int g = lane >> 2, q = lane & 3;
    const int q0 = blockIdx.x * 64;
    const int h  = blockIdx.y;
    const int b  = blockIdx.z;
    const int wb = wid * 16;
    const int bh = b * H_ + h;
    const unsigned sw = (g & 1) << 2;

    // Q fragments straight from packed global (no smem)
    const float* Qp = g_Q + (size_t)(bh * S_ + q0 + wb) * 64;
    unsigned qa[8][4];
#pragma unroll
    for (int p = 0; p < 4; p++) {
        float4 AR = *(const float4*)(Qp + (g    ) * 64 + (q * 4 + p) * 4);
        float4 BR = *(const float4*)(Qp + (g + 8) * 64 + (q * 4 + p) * 4);
        qa[2*p  ][0] = uf(AR.x); qa[2*p  ][1] = uf(BR.x);
        qa[2*p  ][2] = uf(AR.y); qa[2*p  ][3] = uf(BR.y);
        qa[2*p+1][0] = uf(AR.z); qa[2*p+1][1] = uf(BR.z);
        qa[2*p+1][2] = uf(AR.w); qa[2*p+1][3] = uf(BR.w);
    }
    const bool mr1 = mask[b*S_ + q0 + wb + g    ] != 0;
    const bool mr2 = mask[b*S_ + q0 + wb + g + 8] != 0;

    float m1 = -INFINITY, m2 = -INFINITY, l1 = 0.0f, l2 = 0.0f;
    float o[8][4];
#pragma unroll
    for (int j = 0; j < 8; j++)
#pragma unroll
        for (int k = 0; k < 4; k++) o[j][k] = 0.0f;

    const float4* K4 = (const float4*)(g_K + (size_t)bh * S_ * 64);
    const float*  Vt = g_V + (size_t)bh * 64 * S_;

    const int srcA = (lane & ~3) | (q >> 1);
    const int srcB = srcA + 2;
    const bool hi  = q & 1;

    for (int kt = 0; kt < S_ / 64; kt++) {
        __syncthreads();
#pragma unroll
        for (int t = 0; t < 8; t++) {
            int id  = tid + t * 128;
            int row = id >> 4, c16 = id & 15;
            int ph  = (c16 ^ ((row & 1) << 2)) << 2;
            float4 kv = K4[(size_t)(kt * 64 + row) * 16 + c16];
            *(float4*)(Ks + row * 64 + ph) = kv;
            float4 vv = *(const float4*)(Vt + (size_t)row * S_ + kt * 64 + c16 * 4);
            *(float4*)(Vs + row * 64 + ph) = vv;
        }
        if (tid < 64) mks[tid] = mask[b*S_ + kt*64 + tid];
        __syncthreads();

        // S = Q @ K^T
        float s[8][4];
#pragma unroll
        for (int j = 0; j < 8; j++) {
            s[j][0] = s[j][1] = s[j][2] = s[j][3] = 0.0f;
            const float* Kr = Ks + (j * 8 + g) * 64;
#pragma unroll
            for (int t = 0; t < 4; t++) {
                int kkp = (t + q) & 3;
                float4 w = *(const float4*)(Kr + (((q * 4 + kkp) ^ sw) << 2));
                mma8(s[j], qa[2*kkp  ], uf(w.x), uf(w.y));
                mma8(s[j], qa[2*kkp+1], uf(w.z), uf(w.w));
            }
        }

        // mask
#pragma unroll
        for (int j = 0; j < 8; j++) {
            int c0 = j * 8 + 2 * q;
            bool k0m = mks[c0] != 0, k1m = mks[c0 + 1] != 0;
            s[j][0] = (mr1 && k0m) ? s[j][0] : NEGV;
            s[j][1] = (mr1 && k1m) ? s[j][1] : NEGV;
            s[j][2] = (mr2 && k0m) ? s[j][2] : NEGV;
            s[j][3] = (mr2 && k1m) ? s[j][3] : NEGV;
        }

        // online softmax
        float t1 = -INFINITY, t2 = -INFINITY;
#pragma unroll
        for (int j = 0; j < 8; j++) {
            t1 = fmaxf(t1, fmaxf(s[j][0], s[j][1]));
            t2 = fmaxf(t2, fmaxf(s[j][2], s[j][3]));
        }
        t1 = fmaxf(t1, __shfl_xor_sync(0xffffffffu, t1, 1));
        t1 = fmaxf(t1, __shfl_xor_sync(0xffffffffu, t1, 2));
        t2 = fmaxf(t2, __shfl_xor_sync(0xffffffffu, t2, 1));
        t2 = fmaxf(t2, __shfl_xor_sync(0xffffffffu, t2, 2));

        float n1 = fmaxf(m1, t1), n2 = fmaxf(m2, t2);
        float a1 = __expf(m1 - n1), a2 = __expf(m2 - n2);
        m1 = n1; m2 = n2;

        float r1 = 0.0f, r2 = 0.0f;
#pragma unroll
        for (int j = 0; j < 8; j++) {
            s[j][0] = __expf(s[j][0] - n1); s[j][1] = __expf(s[j][1] - n1);
            s[j][2] = __expf(s[j][2] - n2); s[j][3] = __expf(s[j][3] - n2);
            r1 += s[j][0] + s[j][1];
            r2 += s[j][2] + s[j][3];
        }
        r1 += __shfl_xor_sync(0xffffffffu, r1, 1);
        r1 += __shfl_xor_sync(0xffffffffu, r1, 2);
        r2 += __shfl_xor_sync(0xffffffffu, r2, 1);
        r2 += __shfl_xor_sync(0xffffffffu, r2, 2);
        l1 = l1 * a1 + r1;
        l2 = l2 * a2 + r2;
#pragma unroll
        for (int j = 0; j < 8; j++) {
            o[j][0] *= a1; o[j][1] *= a1; o[j][2] *= a2; o[j][3] *= a2;
        }

        // P: C-layout -> A-fragment via shuffles (no smem)
        unsigned pa[8][4];
#pragma unroll
        for (int kk = 0; kk < 8; kk++) {
            float u0 = __shfl_sync(0xffffffffu, s[kk][0], srcA);
            float u1 = __shfl_sync(0xffffffffu, s[kk][1], srcA);
            float u2 = __shfl_sync(0xffffffffu, s[kk][2], srcA);
            float u3 = __shfl_sync(0xffffffffu, s[kk][3], srcA);
            float v0 = __shfl_sync(0xffffffffu, s[kk][0], srcB);
            float v1 = __shfl_sync(0xffffffffu, s[kk][1], srcB);
            float v2 = __shfl_sync(0xffffffffu, s[kk][2], srcB);
            float v3 = __shfl_sync(0xffffffffu, s[kk][3], srcB);
            pa[kk][0] = f2tf(hi ? u1 : u0);
            pa[kk][1] = f2tf(hi ? u3 : u2);
            pa[kk][2] = f2tf(hi ? v1 : v0);
            pa[kk][3] = f2tf(hi ? v3 : v2);
        }

        // O += P @ V  (V^T packed in smem)
#pragma unroll
        for (int j = 0; j < 8; j++) {
            const float* Vr = Vs + (j * 8 + g) * 64;
#pragma unroll
            for (int t = 0; t < 4; t++) {
                int kkp = (t + q) & 3;
                float4 w = *(const float4*)(Vr + (((q * 4 + kkp) ^ sw) << 2));
                mma8(o[j], pa[2*kkp  ], uf(w.x), uf(w.y));
                mma8(o[j], pa[2*kkp+1], uf(w.z), uf(w.w));
            }
        }
    }

    // epilogue
    float i1 = 1.0f / l1, i2 = 1.0f / l2;
    int r1g = q0 + wb + g, r2g = r1g + 8;
#pragma unroll
    for (int j = 0; j < 8; j++) {
        int col = h * 64 + j * 8 + 2 * q;
        *(float2*)(g_ctx + (size_t)(b*S_ + r1g) * D_ + col) = make_float2(o[j][0]*i1, o[j][1]*i1);
        *(float2*)(g_ctx + (size_t)(b*S_ + r2g) * D_ + col) = make_float2(o[j][2]*i2, o[j][3]*i2);
    }
}

// ---------------- host ----------------
extern "C" void kernel_launch(void* const* d_in, const int* in_sizes, int n_in,
                              void* d_out, int out_size)
{
    const float* query = (const float*)d_in[0];
    const float* key   = (const float*)d_in[1];
    const float* value = (const float*)d_in[2];
    const int*   mask  = (const int*)  d_in[3];
    const float* wq = (const float*)d_in[4];
    const float* bq = (const float*)d_in[5];
    const float* wk = (const float*)d_in[6];
    const float* bk = (const float*)d_in[7];
    const float* wv = (const float*)d_in[8];
    const float* bv = (const float*)d_in[9];
    const float* wo = (const float*)d_in[10];
    const float* bo = (const float*)d_in[11];

    float *gQ, *gK, *gV, *gctx;
    cudaGetSymbolAddress((void**)&gQ,   g_Q);
    cudaGetSymbolAddress((void**)&gK,   g_K);
    cudaGetSymbolAddress((void**)&gV,   g_V);
    cudaGetSymbolAddress((void**)&gctx, g_ctx);

    dim3 gg(GN / 128, 4096 / 128);   // (8, 32)

    gemm_tf32<<<gg, 256>>>(query, wq, bq, 0.125f, gQ, 1);  // Q packed, scale folded
    gemm_tf32<<<gg, 256>>>(key,   wk, bk, 1.0f,   gK, 1);  // K packed
    gemm_tf32<<<gg, 256>>>(value, wv, bv, 1.0f,   gV, 2);  // V transposed packed

    attn_tf32<<<dim3(S_/64, H_, B_), 128>>>(mask);

    gemm_tf32<<<gg, 256>>>(gctx, wo, bo, 1.0f, (float*)d_out, 0);
}